// round 14
// baseline (speedup 1.0000x reference)
#include <cuda_runtime.h>
#include <cuda_fp16.h>
#include <cstdint>

typedef unsigned long long u64;
typedef __half f16;
#define DI __device__ __forceinline__

// --------------------------- mma / ldmatrix / cp.async ---------------------
DI uint32_t s2u(const void* p) {
    uint32_t a;
    asm("{ .reg .u64 t; cvta.to.shared.u64 t, %1; cvt.u32.u64 %0, t; }"
        : "=r"(a) : "l"(p));
    return a;
}

DI void mma_f16(float* c, const uint32_t* a, const uint32_t* b) {
    asm volatile(
        "mma.sync.aligned.m16n8k16.row.col.f32.f16.f16.f32 "
        "{%0,%1,%2,%3}, {%4,%5,%6,%7}, {%8,%9}, {%0,%1,%2,%3};"
        : "+f"(c[0]), "+f"(c[1]), "+f"(c[2]), "+f"(c[3])
        : "r"(a[0]), "r"(a[1]), "r"(a[2]), "r"(a[3]), "r"(b[0]), "r"(b[1]));
}

DI void ldsm4(uint32_t* r, uint32_t addr) {
    asm volatile("ldmatrix.sync.aligned.m8n8.x4.shared.b16 {%0,%1,%2,%3}, [%4];"
                 : "=r"(r[0]), "=r"(r[1]), "=r"(r[2]), "=r"(r[3]) : "r"(addr));
}
DI void ldsm4t(uint32_t* r, uint32_t addr) {
    asm volatile("ldmatrix.sync.aligned.m8n8.x4.trans.shared.b16 {%0,%1,%2,%3}, [%4];"
                 : "=r"(r[0]), "=r"(r[1]), "=r"(r[2]), "=r"(r[3]) : "r"(addr));
}

DI void cpa16(uint32_t saddr, const void* g) {
    asm volatile("cp.async.cg.shared.global [%0], [%1], 16;"
                 :: "r"(saddr), "l"(g) : "memory");
}
#define CP_COMMIT() asm volatile("cp.async.commit_group;" ::: "memory")
#define CP_WAIT0()  asm volatile("cp.async.wait_group 0;" ::: "memory")
#define CP_WAIT1()  asm volatile("cp.async.wait_group 1;" ::: "memory")

#define SWZ(x) ((x) ^ (((x) >> 3) & 0x70))

DI uint32_t pkh2(float lo, float hi) {
    uint32_t r;
    asm("cvt.rn.f16x2.f32 %0, %1, %2;" : "=r"(r) : "f"(hi), "f"(lo));
    return r;
}

// ------------------------------ scratch -----------------------------------
#define NTOK 4096
#define DM   1024
#define DFF  4096

__device__ float g_t0[NTOK * DM];
__device__ float g_x1[NTOK * DM];
__device__ int   g_mask_mode;
__device__ u64   g_mpack[(size_t)2 * 16 * 2048 * 32];

__device__ f16 g_x16[NTOK * DM];
__device__ f16 g_qkv[(size_t)NTOK * 3 * DM];
__device__ f16 g_ctx16[NTOK * DM];
__device__ f16 g_x116[NTOK * DM];
__device__ f16 g_h16[(size_t)NTOK * DFF];

__device__ f16 g_wch[3 * DM * DM];
__device__ f16 g_woh[DM * DM];
__device__ f16 g_w1h[DM * DFF];
__device__ f16 g_w2h[DFF * DM];
__device__ float g_bcat[3 * DM];

// ------------------------- mask dtype detection ---------------------------
__global__ void detect_mask_kernel(const unsigned int* __restrict__ w) {
    __shared__ int ok[4];
    const int tid = threadIdx.x;
    if (tid < 4) ok[tid] = 1;
    __syncthreads();
    int li = 1, lf = 1, lb = 1;
    for (int i = tid; i < 4096; i += 256) {
        unsigned v = w[i];
        li &= (v <= 1u);
        lf &= (v == 0u || v == 0x3F800000u);
        unsigned h0 = v & 0xFFFFu, h1 = v >> 16;
        lb &= (int)((h0 == 0u || h0 == 0x3F80u) && (h1 == 0u || h1 == 0x3F80u));
    }
    if (!li) atomicAnd(&ok[0], 0);
    if (!lf) atomicAnd(&ok[1], 0);
    if (!lb) atomicAnd(&ok[2], 0);
    __syncthreads();
    if (tid == 0) {
        int mode;
        if (ok[0])      mode = 1;   // int32
        else if (ok[1]) mode = 2;   // fp32
        else if (ok[2]) mode = 3;   // bf16
        else            mode = 0;   // u8
        g_mask_mode = mode;
    }
}

// ---------------------------- mask bit-packing -----------------------------
__global__ void __launch_bounds__(256)
pack_mask_kernel(const void* __restrict__ mask) {
    const int mode = g_mask_mode;
    const size_t w = (size_t)blockIdx.x * 256 + threadIdx.x;
    const size_t e0 = w << 6;
    u64 bits = 0;
    if (mode == 1) {
        const uint4* p = (const uint4*)((const int*)mask + e0);
#pragma unroll
        for (int i = 0; i < 16; ++i) {
            uint4 v = p[i];
            bits |= (u64)(v.x != 0u) << (i * 4);
            bits |= (u64)(v.y != 0u) << (i * 4 + 1);
            bits |= (u64)(v.z != 0u) << (i * 4 + 2);
            bits |= (u64)(v.w != 0u) << (i * 4 + 3);
        }
    } else if (mode == 0) {
        const uint4* p = (const uint4*)((const unsigned char*)mask + e0);
#pragma unroll
        for (int i = 0; i < 4; ++i) {
            uint4 v = p[i];
            uint32_t ws[4] = {v.x, v.y, v.z, v.w};
#pragma unroll
            for (int j = 0; j < 4; ++j) {
                uint32_t x = ws[j];
                int base = i * 16 + j * 4;
                bits |= (u64)((x & 0x000000FFu) != 0u) << base;
                bits |= (u64)((x & 0x0000FF00u) != 0u) << (base + 1);
                bits |= (u64)((x & 0x00FF0000u) != 0u) << (base + 2);
                bits |= (u64)((x & 0xFF000000u) != 0u) << (base + 3);
            }
        }
    } else if (mode == 2) {
        const float4* p = (const float4*)((const float*)mask + e0);
#pragma unroll
        for (int i = 0; i < 16; ++i) {
            float4 v = p[i];
            bits |= (u64)(v.x != 0.f) << (i * 4);
            bits |= (u64)(v.y != 0.f) << (i * 4 + 1);
            bits |= (u64)(v.z != 0.f) << (i * 4 + 2);
            bits |= (u64)(v.w != 0.f) << (i * 4 + 3);
        }
    } else {
        const uint4* p = (const uint4*)((const unsigned short*)mask + e0);
#pragma unroll
        for (int i = 0; i < 8; ++i) {
            uint4 v = p[i];
            uint32_t ws[4] = {v.x, v.y, v.z, v.w};
#pragma unroll
            for (int j = 0; j < 4; ++j) {
                int base = i * 8 + j * 2;
                bits |= (u64)((ws[j] & 0xFFFFu) != 0u) << base;
                bits |= (u64)((ws[j] >> 16) != 0u) << (base + 1);
            }
        }
    }
    g_mpack[w] = bits;
}

// -------------------- fused prep: bias concat + convT QKV + conv_h ---------
DI void convT_body(const float* __restrict__ W, f16* __restrict__ Th,
                   int K, int N, int n0, int k0)
{
    __shared__ float t[32][33];
    const int tx = threadIdx.x & 31, ty = threadIdx.x >> 5;
#pragma unroll
    for (int i = ty; i < 32; i += 8)
        t[i][tx] = W[(size_t)(k0 + i) * N + n0 + tx];
    __syncthreads();
#pragma unroll
    for (int i = ty; i < 32; i += 8)
        Th[(size_t)(n0 + i) * K + k0 + tx] = __float2half_rn(t[tx][i]);
}

__global__ void __launch_bounds__(256)
prep_qkv_kernel(const float* __restrict__ x, f16* __restrict__ x16,
                const float* __restrict__ Wq, const float* __restrict__ Wk,
                const float* __restrict__ Wv, f16* __restrict__ wch,
                const float* __restrict__ bq, const float* __restrict__ bk,
                const float* __restrict__ bv, float* __restrict__ bcat)
{
    int bx = blockIdx.x;
    if (bx < 3) {
        const float* src = bx == 0 ? bq : (bx == 1 ? bk : bv);
        ((float4*)(bcat + (bx << 10)))[threadIdx.x] = ((const float4*)src)[threadIdx.x];
        return;
    }
    bx -= 3;
    if (bx < 3072) {
        const int wsel = bx >> 10;
        const float* W = wsel == 0 ? Wq : (wsel == 1 ? Wk : Wv);
        f16* Th = wch + (size_t)wsel * DM * DM;
        const int t = bx & 1023;
        const int n0 = (t & 31) << 5, k0 = (t >> 5) << 5;
        convT_body(W, Th, DM, DM, n0, k0);
        return;
    }
    bx -= 3072;
    const int i = bx * 256 + threadIdx.x;
    float4 v = ((const float4*)x)[i];
    uint2 ph;
    ph.x = pkh2(v.x, v.y);
    ph.y = pkh2(v.z, v.w);
    ((uint2*)x16)[i] = ph;
}

// ------------------- fused convT for Wo / W1 / W2 (side stream) ------------
__global__ void __launch_bounds__(256)
convT_ffn_kernel(const float* __restrict__ Wo, f16* __restrict__ woh,
                 const float* __restrict__ W1, f16* __restrict__ w1h,
                 const float* __restrict__ W2, f16* __restrict__ w2h)
{
    int bx = blockIdx.x;
    if (bx < 1024) {
        const int n0 = (bx & 31) << 5, k0 = (bx >> 5) << 5;
        convT_body(Wo, woh, DM, DM, n0, k0);
        return;
    }
    bx -= 1024;
    if (bx < 4096) {
        const int n0 = (bx & 127) << 5, k0 = (bx >> 7) << 5;
        convT_body(W1, w1h, DM, DFF, n0, k0);
        return;
    }
    bx -= 4096;
    const int n0 = (bx & 31) << 5, k0 = (bx >> 5) << 5;
    convT_body(W2, w2h, DFF, DM, n0, k0);
}

// ----------------- mma.sync GEMM (fp16, 128x128 tile, 2 CTAs/SM) -----------
#define ST_BYTES 32768u
#define GEMM_SMEM (3 * 32768)

DI void load_stage_async(uint32_t tb, const f16* __restrict__ A,
                         const f16* __restrict__ B, int bm, int bn, int K,
                         int kt, int tid)
{
    const int koff = kt << 6;
#pragma unroll
    for (int i = 0; i < 4; ++i) {
        int idx = tid + (i << 8);
        int row = idx >> 3, c = idx & 7;
        cpa16(tb + SWZ((row << 7) | (c << 4)),
              A + (size_t)(bm + row) * K + koff + (c << 3));
    }
#pragma unroll
    for (int i = 0; i < 4; ++i) {
        int idx = tid + (i << 8);
        int row = idx >> 3, c = idx & 7;
        cpa16(tb + 16384 + SWZ((row << 7) | (c << 4)),
              B + (size_t)(bn + row) * K + koff + (c << 3));
    }
}

template <int RELU, int OUT>
__global__ void __launch_bounds__(256, 2)
gemm_mma_kernel(const f16* __restrict__ A, const f16* __restrict__ B,
                const float* __restrict__ bias, float* __restrict__ Cf,
                f16* __restrict__ Ch, int M, int N, int K)
{
    extern __shared__ char smc[];
    const uint32_t sb = s2u(smc);
    const int tid = threadIdx.x, wid = tid >> 5, lane = tid & 31;
    const int bm = blockIdx.y << 7, bn = blockIdx.x << 7;
    const int mw = (wid & 1) << 6;
    const int nw = (wid >> 1) << 5;

    float acc[4][4][4];
#pragma unroll
    for (int i = 0; i < 4; ++i)
#pragma unroll
        for (int j = 0; j < 4; ++j)
#pragma unroll
            for (int k = 0; k < 4; ++k) acc[i][j][k] = 0.f;

    const int a_r  = (lane & 7) + ((lane & 8) ? 8 : 0);
    const int a_kb = (lane & 16) ? 16 : 0;
    const int b_r  = (lane & 7) + ((lane & 16) ? 8 : 0);
    const int b_kb = (lane & 8) ? 16 : 0;

    uint32_t aoff[4], asw[4];
#pragma unroll
    for (int mi = 0; mi < 4; ++mi) {
        int row = mw + (mi << 4) + a_r;
        aoff[mi] = (uint32_t)(row << 7);
        asw[mi]  = (uint32_t)((row & 7) << 4);
    }
    uint32_t boff[2], bsw[2];
#pragma unroll
    for (int g = 0; g < 2; ++g) {
        int row = nw + (g << 4) + b_r;
        boff[g] = (uint32_t)(row << 7);
        bsw[g]  = (uint32_t)((row & 7) << 4);
    }

    const int KT = K >> 6;
#pragma unroll
    for (int s = 0; s < 2; ++s) {
        load_stage_async(sb + (uint32_t)s * ST_BYTES, A, B, bm, bn, K, s, tid);
        CP_COMMIT();
    }

    int stq = 0;
    for (int kt = 0; kt < KT; ++kt) {
        CP_WAIT1();
        __syncthreads();    // all warps finished previous ktile; tile kt ready
        if (kt + 2 < KT) {
            int sn = stq + 2; if (sn >= 3) sn -= 3;   // == stage of tile kt-1
            load_stage_async(sb + (uint32_t)sn * ST_BYTES,
                             A, B, bm, bn, K, kt + 2, tid);
            CP_COMMIT();
        }
        const uint32_t st = sb + (uint32_t)stq * ST_BYTES;
#pragma unroll
        for (int ks = 0; ks < 4; ++ks) {
            uint32_t fbh[2][4];
#pragma unroll
            for (int g = 0; g < 2; ++g)
                ldsm4(fbh[g], st + 16384 + boff[g] +
                      (((uint32_t)(b_kb + ks * 32)) ^ bsw[g]));
#pragma unroll
            for (int mi = 0; mi < 4; ++mi) {
                uint32_t fah[4];
                ldsm4(fah, st + aoff[mi] + (((uint32_t)(a_kb + ks * 32)) ^ asw[mi]));
#pragma unroll
                for (int nj = 0; nj < 4; ++nj)
                    mma_f16(acc[mi][nj], fah, &fbh[nj >> 1][(nj & 1) << 1]);
            }
        }
        if (++stq == 3) stq = 0;
    }

    const int r0 = lane >> 2, c2 = (lane & 3) << 1;
    float2 bb[4];
#pragma unroll
    for (int nj = 0; nj < 4; ++nj)
        bb[nj] = *(const float2*)(bias + bn + nw + (nj << 3) + c2);
#pragma unroll
    for (int mi = 0; mi < 4; ++mi) {
        const int row = bm + mw + (mi << 4) + r0;
#pragma unroll
        for (int nj = 0; nj < 4; ++nj) {
            const int col = bn + nw + (nj << 3) + c2;
            float v0 = acc[mi][nj][0] + bb[nj].x, v1 = acc[mi][nj][1] + bb[nj].y;
            float v2 = acc[mi][nj][2] + bb[nj].x, v3 = acc[mi][nj][3] + bb[nj].y;
            if (RELU) {
                v0 = fmaxf(v0, 0.f); v1 = fmaxf(v1, 0.f);
                v2 = fmaxf(v2, 0.f); v3 = fmaxf(v3, 0.f);
            }
            if (OUT == 0) {
                *(float2*)(Cf + (size_t)row * N + col)       = make_float2(v0, v1);
                *(float2*)(Cf + (size_t)(row + 8) * N + col) = make_float2(v2, v3);
            } else {
                *(uint32_t*)(Ch + (size_t)row * N + col)       = pkh2(v0, v1);
                *(uint32_t*)(Ch + (size_t)(row + 8) * N + col) = pkh2(v2, v3);
            }
        }
    }
}

// --------------------------- flash attention (mma fp16) --------------------
// CTA: 128 threads (4 warps), 128 q-rows; warp tile 32q x 64k.
// K/V fragments amortized over 2x q -> LDSM traffic per MAC halved.
__global__ void __launch_bounds__(128, 2)
flash_mma_kernel(const f16* __restrict__ qkv, const u64* __restrict__ mpack,
                 f16* __restrict__ ctx)
{
    __shared__ f16 sQ[128 * 64];     // 16 KB
    __shared__ f16 sK[2][64 * 64];   // 16 KB
    __shared__ f16 sV[2][64 * 64];   // 16 KB

    const int tid = threadIdx.x, wid = tid >> 5, lane = tid & 31;
    const int q0 = blockIdx.x << 7;
    const int h  = blockIdx.y;
    const int b  = blockIdx.z;

    const uint32_t sqb = s2u(sQ);
    const uint32_t skb[2] = {s2u(sK[0]), s2u(sK[1])};
    const uint32_t svb[2] = {s2u(sV[0]), s2u(sV[1])};

    const f16* Qg = qkv + (size_t)(b * 2048) * 3072 + (h << 6);
    const f16* Kg = Qg + 1024;
    const f16* Vg = Qg + 2048;

    // Q tile: 128 rows x 64 f16 -> 1024 16B chunks / 128 thr = 8 each
#pragma unroll
    for (int i = 0; i < 8; ++i) {
        int idx = tid + (i << 7);
        int row = idx >> 3, c = idx & 7;
        cpa16(sqb + SWZ((row << 7) | (c << 4)),
              Qg + (size_t)(q0 + row) * 3072 + (c << 3));
    }
    CP_COMMIT();
#pragma unroll
    for (int s = 0; s < 2; ++s) {
#pragma unroll
        for (int i = 0; i < 4; ++i) {
            int idx = tid + (i << 7);
            int row = idx >> 3, c = idx & 7;
            size_t go = (size_t)(s * 64 + row) * 3072 + (c << 3);
            uint32_t d = SWZ((row << 7) | (c << 4));
            cpa16(skb[s] + d, Kg + go);
            cpa16(svb[s] + d, Vg + go);
        }
        CP_COMMIT();
    }
    CP_WAIT1();
    __syncthreads();

    const int a_r  = lane & 15;
    const int a_kb = (lane & 16) ? 16 : 0;
    uint32_t qf[2][4][4];
#pragma unroll
    for (int mi = 0; mi < 2; ++mi) {
        const int row = (wid << 5) + (mi << 4) + a_r;
        const uint32_t ro = (uint32_t)(row << 7);
        const uint32_t sw = (uint32_t)((row & 7) << 4);
#pragma unroll
        for (int kk = 0; kk < 4; ++kk)
            ldsm4(qf[mi][kk], sqb + ro + (((uint32_t)(a_kb + kk * 32)) ^ sw));
    }

    const int b_r  = (lane & 7) + ((lane & 16) ? 8 : 0);
    const int b_kb = (lane & 8) ? 16 : 0;
    const int v_r  = (lane & 7) + ((lane & 8) ? 8 : 0);
    const int v_kb = (lane & 16) ? 16 : 0;

    const int r0 = lane >> 2, c2 = (lane & 3) << 1;
    const int qrow0 = q0 + (wid << 5) + r0;     // rows qrow0 + {0,8,16,24}
    float l[4] = {0.f, 0.f, 0.f, 0.f};
    float acc[2][8][4];
#pragma unroll
    for (int mi = 0; mi < 2; ++mi)
#pragma unroll
        for (int nt = 0; nt < 8; ++nt)
#pragma unroll
            for (int k = 0; k < 4; ++k) acc[mi][nt][k] = 0.f;

    const u64* mpr = mpack + ((size_t)((b << 4) + h) * 2048 + qrow0) * 32;

    for (int kt = 0; kt < 32; ++kt) {
        const int st = kt & 1;
        u64 w[4];
#pragma unroll
        for (int j = 0; j < 4; ++j) w[j] = mpr[(size_t)(j << 3) * 32 + kt];

        // ---- S = Q K^T (K frags shared across both mi groups) ----
        float s[2][8][4];
#pragma unroll
        for (int mi = 0; mi < 2; ++mi)
#pragma unroll
            for (int nt = 0; nt < 8; ++nt)
#pragma unroll
                for (int k = 0; k < 4; ++k) s[mi][nt][k] = 0.f;
#pragma unroll
        for (int kk = 0; kk < 4; ++kk) {
            uint32_t kf[4][4];
#pragma unroll
            for (int g = 0; g < 4; ++g) {
                int row = (g << 4) + b_r;
                ldsm4(kf[g], skb[st] + (uint32_t)(row << 7) +
                      (((uint32_t)(b_kb + kk * 32)) ^ ((uint32_t)((row & 7) << 4))));
            }
#pragma unroll
            for (int g = 0; g < 4; ++g) {
#pragma unroll
                for (int mi = 0; mi < 2; ++mi) {
                    mma_f16(s[mi][2 * g],     qf[mi][kk], &kf[g][0]);
                    mma_f16(s[mi][2 * g + 1], qf[mi][kk], &kf[g][2]);
                }
            }
        }

        // ---- mask + exp (max-free) ----
#pragma unroll
        for (int mi = 0; mi < 2; ++mi) {
            const u64 wa = w[2 * mi], wb = w[2 * mi + 1];
#pragma unroll
            for (int nt = 0; nt < 8; ++nt) {
                const int sh = c2 + (nt << 3);
                s[mi][nt][0] = ((wa >> sh) & 1)       ? __expf(s[mi][nt][0] * 0.125f) : 0.f;
                s[mi][nt][1] = ((wa >> (sh + 1)) & 1) ? __expf(s[mi][nt][1] * 0.125f) : 0.f;
                s[mi][nt][2] = ((wb >> sh) & 1)       ? __expf(s[mi][nt][2] * 0.125f) : 0.f;
                s[mi][nt][3] = ((wb >> (sh + 1)) & 1) ? __expf(s[mi][nt][3] * 0.125f) : 0.f;
                l[2 * mi]     += s[mi][nt][0] + s[mi][nt][1];
                l[2 * mi + 1] += s[mi][nt][2] + s[mi][nt][3];
            }
        }

        // ---- ctx += P V (V frags shared across mi) ----
#pragma unroll
        for (int kk = 0; kk < 4; ++kk) {
            uint32_t ap[2][4];
#pragma unroll
            for (int mi = 0; mi < 2; ++mi) {
                ap[mi][0] = pkh2(s[mi][2 * kk][0],     s[mi][2 * kk][1]);
                ap[mi][1] = pkh2(s[mi][2 * kk][2],     s[mi][2 * kk][3]);
                ap[mi][2] = pkh2(s[mi][2 * kk + 1][0], s[mi][2 * kk + 1][1]);
                ap[mi][3] = pkh2(s[mi][2 * kk + 1][2], s[mi][2 * kk + 1][3]);
            }
            uint32_t vf[4][4];
#pragma unroll
            for (int g = 0; g < 4; ++g) {
                int row = (kk << 4) + v_r;
                ldsm4t(vf[g], svb[st] + (uint32_t)(row << 7) +
                       (((uint32_t)(v_kb + g * 32)) ^ ((uint32_t)((row & 7) << 4))));
            }
#pragma unroll
            for (int g = 0; g < 4; ++g) {
#pragma unroll
                for (int mi = 0; mi < 2; ++mi) {
                    mma_f16(acc[mi][2 * g],     ap[mi], &vf[g][0]);
                    mma_f16(acc[mi][2 * g + 1], ap[mi], &vf[g][2]);
                }
            }
        }

        __syncthreads();
        if (kt + 2 < 32) {
#pragma unroll
            for (int i = 0; i < 4; ++i) {
                int idx = tid + (i << 7);
                int row = idx >> 3, c = idx & 7;
                size_t go = (size_t)((kt + 2) * 64 + row) * 3072 + (c << 3);
                uint32_t d = SWZ((row << 7) | (c << 4));
                cpa16(skb[st] + d, Kg + go);
                cpa16(svb[st] + d, Vg + go);
            }
            CP_COMMIT();
            CP_WAIT1();
        } else {
            CP_WAIT0();
        }
        __syncthreads();
    }

#pragma unroll
    for (int j = 0; j < 4; ++j) {
        l[j] += __shfl_xor_sync(0xffffffffu, l[j], 1);
        l[j] += __shfl_xor_sync(0xffffffffu, l[j], 2);
    }

    const size_t rowb = (size_t)(b * 2048 + qrow0) * 1024 + (h << 6) + c2;
#pragma unroll
    for (int mi = 0; mi < 2; ++mi) {
        const float i0 = 1.0f / l[2 * mi], i1 = 1.0f / l[2 * mi + 1];
        const size_t row0 = rowb + (size_t)(mi << 4) * 1024;
        const size_t row1 = row0 + 8 * 1024;
#pragma unroll
        for (int nt = 0; nt < 8; ++nt) {
            *(uint32_t*)(ctx + row0 + (nt << 3)) =
                pkh2(acc[mi][nt][0] * i0, acc[mi][nt][1] * i0);
            *(uint32_t*)(ctx + row1 + (nt << 3)) =
                pkh2(acc[mi][nt][2] * i1, acc[mi][nt][3] * i1);
        }
    }
}

// --------------------------- residual + LN --------------------------------
DI float block_sum256(float v, float* red) {
#pragma unroll
    for (int o = 16; o > 0; o >>= 1) v += __shfl_xor_sync(0xffffffffu, v, o);
    const int w = threadIdx.x >> 5;
    if ((threadIdx.x & 31) == 0) red[w] = v;
    __syncthreads();
    if (threadIdx.x < 8) {
        float t = red[threadIdx.x];
#pragma unroll
        for (int o = 4; o > 0; o >>= 1) t += __shfl_xor_sync(0x000000ffu, t, o);
        if (threadIdx.x == 0) red[0] = t;
    }
    __syncthreads();
    float r = red[0];
    __syncthreads();
    return r;
}

template <int SPLIT>
__global__ void __launch_bounds__(256)
add_ln_kernel(const float* __restrict__ X, const float* __restrict__ R,
              const float* __restrict__ g, const float* __restrict__ bt,
              float* __restrict__ out, f16* __restrict__ H)
{
    __shared__ float red[8];
    const int row = blockIdx.x, tid = threadIdx.x;
    const float4 xv = ((const float4*)(X + (size_t)row * 1024))[tid];
    const float4 rv = ((const float4*)(R + (size_t)row * 1024))[tid];
    float v0 = xv.x + rv.x, v1 = xv.y + rv.y, v2 = xv.z + rv.z, v3 = xv.w + rv.w;
    float tot = block_sum256(v0 + v1 + v2 + v3, red);
    const float mu = tot * (1.0f / 1024.0f);
    float d0 = v0 - mu, d1 = v1 - mu, d2 = v2 - mu, d3 = v3 - mu;
    float sq = block_sum256(d0 * d0 + d1 * d1 + d2 * d2 + d3 * d3, red);
    const float rs = rsqrtf(sq * (1.0f / 1024.0f) + 1e-5f);
    const float4 gv = ((const float4*)g)[tid];
    const float4 bv = ((const float4*)bt)[tid];
    float o0 = d0 * rs * gv.x + bv.x, o1 = d1 * rs * gv.y + bv.y;
    float o2 = d2 * rs * gv.z + bv.z, o3 = d3 * rs * gv.w + bv.w;
    ((float4*)(out + (size_t)row * 1024))[tid] = make_float4(o0, o1, o2, o3);
    if (SPLIT) {
        uint2 ph = make_uint2(pkh2(o0, o1), pkh2(o2, o3));
        ((uint2*)(H + (size_t)row * 1024))[tid] = ph;
    }
}

// ------------------------------ launcher -----------------------------------
extern "C" void kernel_launch(void* const* d_in, const int* in_sizes, int n_in,
                              void* d_out, int out_size)
{
    const float* x    = (const float*)d_in[0];
    const void*  mask = d_in[1];
    const float* Wq = (const float*)d_in[2];  const float* bq = (const float*)d_in[3];
    const float* Wk = (const float*)d_in[4];  const float* bk = (const float*)d_in[5];
    const float* Wv = (const float*)d_in[6];  const float* bv = (const float*)d_in[7];
    const float* Wo = (const float*)d_in[8];  const float* bo = (const float*)d_in[9];
    const float* ln1g = (const float*)d_in[10]; const float* ln1b = (const float*)d_in[11];
    const float* ln2g = (const float*)d_in[12]; const float* ln2b = (const float*)d_in[13];
    const float* W1 = (const float*)d_in[14]; const float* b1 = (const float*)d_in[15];
    const float* W2 = (const float*)d_in[16]; const float* b2 = (const float*)d_in[17];
    float* out = (float*)d_out;

    static bool init_done = false;
    static cudaStream_t s1, s2;
    static cudaEvent_t evRoot, evPack, evW;
    if (!init_done) {
        cudaFuncSetAttribute(gemm_mma_kernel<0, 0>, cudaFuncAttributeMaxDynamicSharedMemorySize, GEMM_SMEM);
        cudaFuncSetAttribute(gemm_mma_kernel<0, 1>, cudaFuncAttributeMaxDynamicSharedMemorySize, GEMM_SMEM);
        cudaFuncSetAttribute(gemm_mma_kernel<1, 1>, cudaFuncAttributeMaxDynamicSharedMemorySize, GEMM_SMEM);
        cudaStreamCreateWithFlags(&s1, cudaStreamNonBlocking);
        cudaStreamCreateWithFlags(&s2, cudaStreamNonBlocking);
        cudaEventCreateWithFlags(&evRoot, cudaEventDisableTiming);
        cudaEventCreateWithFlags(&evPack, cudaEventDisableTiming);
        cudaEventCreateWithFlags(&evW,    cudaEventDisableTiming);
        init_done = true;
    }

    float *t0p, *x1p, *bcat;
    u64* mpk;
    f16 *x16, *qkvp, *ctx16, *x116, *h16;
    f16 *wch, *woh, *w1h, *w2h;
    cudaGetSymbolAddress((void**)&t0p, g_t0);
    cudaGetSymbolAddress((void**)&x1p, g_x1);
    cudaGetSymbolAddress((void**)&bcat, g_bcat);
    cudaGetSymbolAddress((void**)&mpk, g_mpack);
    cudaGetSymbolAddress((void**)&x16, g_x16);
    cudaGetSymbolAddress((void**)&qkvp, g_qkv);
    cudaGetSymbolAddress((void**)&ctx16, g_ctx16);
    cudaGetSymbolAddress((void**)&x116, g_x116);
    cudaGetSymbolAddress((void**)&h16, g_h16);
    cudaGetSymbolAddress((void**)&wch, g_wch);
    cudaGetSymbolAddress((void**)&woh, g_woh);
    cudaGetSymbolAddress((void**)&w1h, g_w1h);
    cudaGetSymbolAddress((void**)&w2h, g_w2h);

    // #1 detect
    detect_mask_kernel<<<1, 256>>>((const unsigned int*)mask);
    cudaEventRecord(evRoot, 0);

    // #2 pack (side stream 1)
    cudaStreamWaitEvent(s1, evRoot, 0);
    pack_mask_kernel<<<8192, 256, 0, s1>>>(mask);
    cudaEventRecord(evPack, s1);

    // #3 fused prep
    prep_qkv_kernel<<<3 + 3072 + 4096, 256>>>(x, x16, Wq, Wk, Wv, wch,
                                              bq, bk, bv, bcat);

    // #4 fused QKV GEMM
    gemm_mma_kernel<0, 1><<<dim3(3 * DM / 128, NTOK / 128), 256, GEMM_SMEM>>>(
        x16, wch, bcat, nullptr, qkvp, NTOK, 3 * DM, DM);

    // #5 flash
    cudaStreamWaitEvent(0, evPack, 0);
    flash_mma_kernel<<<dim3(16, 16, 2), 128>>>(qkvp, mpk, ctx16);

    // #6 FFN-weight transposes (side stream 2)
    cudaStreamWaitEvent(s2, evRoot, 0);
    convT_ffn_kernel<<<1024 + 4096 + 4096, 256, 0, s2>>>(Wo, woh, W1, w1h, W2, w2h);
    cudaEventRecord(evW, s2);

    cudaStreamWaitEvent(0, evW, 0);
    gemm_mma_kernel<0, 0><<<dim3(DM / 128, NTOK / 128), 256, GEMM_SMEM>>>(
        ctx16, woh, bo, t0p, nullptr, NTOK, DM, DM);
    add_ln_kernel<1><<<NTOK, 256>>>(x, t0p, ln1g, ln1b, x1p, x116);

    gemm_mma_kernel<1, 1><<<dim3(DFF / 128, NTOK / 128), 256, GEMM_SMEM>>>(
        x116, w1h, b1, nullptr, h16, NTOK, DFF, DM);
    gemm_mma_kernel<0, 0><<<dim3(DM / 128, NTOK / 128), 256, GEMM_SMEM>>>(
        h16, w2h, b2, t0p, nullptr, NTOK, DM, DFF);
    add_ln_kernel<0><<<NTOK, 256>>>(x1p, t0p, ln2g, ln2b, out, nullptr);
}

// round 15
// speedup vs baseline: 1.0766x; 1.0766x over previous
#include <cuda_runtime.h>
#include <cuda_fp16.h>
#include <cstdint>

typedef unsigned long long u64;
typedef __half f16;
#define DI __device__ __forceinline__

// --------------------------- mma / ldmatrix / cp.async ---------------------
DI uint32_t s2u(const void* p) {
    uint32_t a;
    asm("{ .reg .u64 t; cvta.to.shared.u64 t, %1; cvt.u32.u64 %0, t; }"
        : "=r"(a) : "l"(p));
    return a;
}

DI void mma_f16(float* c, const uint32_t* a, const uint32_t* b) {
    asm volatile(
        "mma.sync.aligned.m16n8k16.row.col.f32.f16.f16.f32 "
        "{%0,%1,%2,%3}, {%4,%5,%6,%7}, {%8,%9}, {%0,%1,%2,%3};"
        : "+f"(c[0]), "+f"(c[1]), "+f"(c[2]), "+f"(c[3])
        : "r"(a[0]), "r"(a[1]), "r"(a[2]), "r"(a[3]), "r"(b[0]), "r"(b[1]));
}

DI void ldsm4(uint32_t* r, uint32_t addr) {
    asm volatile("ldmatrix.sync.aligned.m8n8.x4.shared.b16 {%0,%1,%2,%3}, [%4];"
                 : "=r"(r[0]), "=r"(r[1]), "=r"(r[2]), "=r"(r[3]) : "r"(addr));
}
DI void ldsm4t(uint32_t* r, uint32_t addr) {
    asm volatile("ldmatrix.sync.aligned.m8n8.x4.trans.shared.b16 {%0,%1,%2,%3}, [%4];"
                 : "=r"(r[0]), "=r"(r[1]), "=r"(r[2]), "=r"(r[3]) : "r"(addr));
}

DI void cpa16(uint32_t saddr, const void* g) {
    asm volatile("cp.async.cg.shared.global [%0], [%1], 16;"
                 :: "r"(saddr), "l"(g) : "memory");
}
#define CP_COMMIT() asm volatile("cp.async.commit_group;" ::: "memory")
#define CP_WAIT0()  asm volatile("cp.async.wait_group 0;" ::: "memory")
#define CP_WAIT1()  asm volatile("cp.async.wait_group 1;" ::: "memory")

#define SWZ(x) ((x) ^ (((x) >> 3) & 0x70))

DI uint32_t pkh2(float lo, float hi) {
    uint32_t r;
    asm("cvt.rn.f16x2.f32 %0, %1, %2;" : "=r"(r) : "f"(hi), "f"(lo));
    return r;
}

// ------------------------------ scratch -----------------------------------
#define NTOK 4096
#define DM   1024
#define DFF  4096

__device__ float g_t0[NTOK * DM];
__device__ float g_x1[NTOK * DM];
__device__ int   g_mask_mode;
__device__ u64   g_mpack[(size_t)2 * 16 * 2048 * 32];

__device__ f16 g_x16[NTOK * DM];
__device__ f16 g_qkv[(size_t)NTOK * 3 * DM];
__device__ f16 g_ctx16[NTOK * DM];
__device__ f16 g_x116[NTOK * DM];
__device__ f16 g_h16[(size_t)NTOK * DFF];

__device__ f16 g_wch[3 * DM * DM];
__device__ f16 g_woh[DM * DM];
__device__ f16 g_w1h[DM * DFF];
__device__ f16 g_w2h[DFF * DM];
__device__ float g_bcat[3 * DM];

// ------------------------- mask dtype detection ---------------------------
__global__ void detect_mask_kernel(const unsigned int* __restrict__ w) {
    __shared__ int ok[4];
    const int tid = threadIdx.x;
    if (tid < 4) ok[tid] = 1;
    __syncthreads();
    int li = 1, lf = 1, lb = 1;
    for (int i = tid; i < 4096; i += 256) {
        unsigned v = w[i];
        li &= (v <= 1u);
        lf &= (v == 0u || v == 0x3F800000u);
        unsigned h0 = v & 0xFFFFu, h1 = v >> 16;
        lb &= (int)((h0 == 0u || h0 == 0x3F80u) && (h1 == 0u || h1 == 0x3F80u));
    }
    if (!li) atomicAnd(&ok[0], 0);
    if (!lf) atomicAnd(&ok[1], 0);
    if (!lb) atomicAnd(&ok[2], 0);
    __syncthreads();
    if (tid == 0) {
        int mode;
        if (ok[0])      mode = 1;   // int32
        else if (ok[1]) mode = 2;   // fp32
        else if (ok[2]) mode = 3;   // bf16
        else            mode = 0;   // u8
        g_mask_mode = mode;
    }
}

// ---------------------------- mask bit-packing -----------------------------
__global__ void __launch_bounds__(256)
pack_mask_kernel(const void* __restrict__ mask) {
    const int mode = g_mask_mode;
    const size_t w = (size_t)blockIdx.x * 256 + threadIdx.x;
    const size_t e0 = w << 6;
    u64 bits = 0;
    if (mode == 1) {
        const uint4* p = (const uint4*)((const int*)mask + e0);
#pragma unroll
        for (int i = 0; i < 16; ++i) {
            uint4 v = p[i];
            bits |= (u64)(v.x != 0u) << (i * 4);
            bits |= (u64)(v.y != 0u) << (i * 4 + 1);
            bits |= (u64)(v.z != 0u) << (i * 4 + 2);
            bits |= (u64)(v.w != 0u) << (i * 4 + 3);
        }
    } else if (mode == 0) {
        const uint4* p = (const uint4*)((const unsigned char*)mask + e0);
#pragma unroll
        for (int i = 0; i < 4; ++i) {
            uint4 v = p[i];
            uint32_t ws[4] = {v.x, v.y, v.z, v.w};
#pragma unroll
            for (int j = 0; j < 4; ++j) {
                uint32_t x = ws[j];
                int base = i * 16 + j * 4;
                bits |= (u64)((x & 0x000000FFu) != 0u) << base;
                bits |= (u64)((x & 0x0000FF00u) != 0u) << (base + 1);
                bits |= (u64)((x & 0x00FF0000u) != 0u) << (base + 2);
                bits |= (u64)((x & 0xFF000000u) != 0u) << (base + 3);
            }
        }
    } else if (mode == 2) {
        const float4* p = (const float4*)((const float*)mask + e0);
#pragma unroll
        for (int i = 0; i < 16; ++i) {
            float4 v = p[i];
            bits |= (u64)(v.x != 0.f) << (i * 4);
            bits |= (u64)(v.y != 0.f) << (i * 4 + 1);
            bits |= (u64)(v.z != 0.f) << (i * 4 + 2);
            bits |= (u64)(v.w != 0.f) << (i * 4 + 3);
        }
    } else {
        const uint4* p = (const uint4*)((const unsigned short*)mask + e0);
#pragma unroll
        for (int i = 0; i < 8; ++i) {
            uint4 v = p[i];
            uint32_t ws[4] = {v.x, v.y, v.z, v.w};
#pragma unroll
            for (int j = 0; j < 4; ++j) {
                int base = i * 8 + j * 2;
                bits |= (u64)((ws[j] & 0xFFFFu) != 0u) << base;
                bits |= (u64)((ws[j] >> 16) != 0u) << (base + 1);
            }
        }
    }
    g_mpack[w] = bits;
}

// -------------------- fused prep: bias concat + convT QKV + conv_h ---------
DI void convT_body(const float* __restrict__ W, f16* __restrict__ Th,
                   int K, int N, int n0, int k0)
{
    __shared__ float t[32][33];
    const int tx = threadIdx.x & 31, ty = threadIdx.x >> 5;
#pragma unroll
    for (int i = ty; i < 32; i += 8)
        t[i][tx] = W[(size_t)(k0 + i) * N + n0 + tx];
    __syncthreads();
#pragma unroll
    for (int i = ty; i < 32; i += 8)
        Th[(size_t)(n0 + i) * K + k0 + tx] = __float2half_rn(t[tx][i]);
}

__global__ void __launch_bounds__(256)
prep_qkv_kernel(const float* __restrict__ x, f16* __restrict__ x16,
                const float* __restrict__ Wq, const float* __restrict__ Wk,
                const float* __restrict__ Wv, f16* __restrict__ wch,
                const float* __restrict__ bq, const float* __restrict__ bk,
                const float* __restrict__ bv, float* __restrict__ bcat)
{
    int bx = blockIdx.x;
    if (bx < 3) {
        const float* src = bx == 0 ? bq : (bx == 1 ? bk : bv);
        ((float4*)(bcat + (bx << 10)))[threadIdx.x] = ((const float4*)src)[threadIdx.x];
        return;
    }
    bx -= 3;
    if (bx < 3072) {
        const int wsel = bx >> 10;
        const float* W = wsel == 0 ? Wq : (wsel == 1 ? Wk : Wv);
        f16* Th = wch + (size_t)wsel * DM * DM;
        const int t = bx & 1023;
        const int n0 = (t & 31) << 5, k0 = (t >> 5) << 5;
        convT_body(W, Th, DM, DM, n0, k0);
        return;
    }
    bx -= 3072;
    const int i = bx * 256 + threadIdx.x;
    float4 v = ((const float4*)x)[i];
    uint2 ph;
    ph.x = pkh2(v.x, v.y);
    ph.y = pkh2(v.z, v.w);
    ((uint2*)x16)[i] = ph;
}

// ------------------- fused convT for Wo / W1 / W2 (side stream) ------------
__global__ void __launch_bounds__(256)
convT_ffn_kernel(const float* __restrict__ Wo, f16* __restrict__ woh,
                 const float* __restrict__ W1, f16* __restrict__ w1h,
                 const float* __restrict__ W2, f16* __restrict__ w2h)
{
    int bx = blockIdx.x;
    if (bx < 1024) {
        const int n0 = (bx & 31) << 5, k0 = (bx >> 5) << 5;
        convT_body(Wo, woh, DM, DM, n0, k0);
        return;
    }
    bx -= 1024;
    if (bx < 4096) {
        const int n0 = (bx & 127) << 5, k0 = (bx >> 7) << 5;
        convT_body(W1, w1h, DM, DFF, n0, k0);
        return;
    }
    bx -= 4096;
    const int n0 = (bx & 31) << 5, k0 = (bx >> 5) << 5;
    convT_body(W2, w2h, DFF, DM, n0, k0);
}

// ----------------- mma.sync GEMM (fp16, 128x128 tile, 2 CTAs/SM) -----------
#define ST_BYTES 32768u
#define GEMM_SMEM (3 * 32768)

DI void load_stage_async(uint32_t tb, const f16* __restrict__ A,
                         const f16* __restrict__ B, int bm, int bn, int K,
                         int kt, int tid)
{
    const int koff = kt << 6;
#pragma unroll
    for (int i = 0; i < 4; ++i) {
        int idx = tid + (i << 8);
        int row = idx >> 3, c = idx & 7;
        cpa16(tb + SWZ((row << 7) | (c << 4)),
              A + (size_t)(bm + row) * K + koff + (c << 3));
    }
#pragma unroll
    for (int i = 0; i < 4; ++i) {
        int idx = tid + (i << 8);
        int row = idx >> 3, c = idx & 7;
        cpa16(tb + 16384 + SWZ((row << 7) | (c << 4)),
              B + (size_t)(bn + row) * K + koff + (c << 3));
    }
}

template <int RELU, int OUT>
__global__ void __launch_bounds__(256, 2)
gemm_mma_kernel(const f16* __restrict__ A, const f16* __restrict__ B,
                const float* __restrict__ bias, float* __restrict__ Cf,
                f16* __restrict__ Ch, int M, int N, int K)
{
    extern __shared__ char smc[];
    const uint32_t sb = s2u(smc);
    const int tid = threadIdx.x, wid = tid >> 5, lane = tid & 31;
    const int bm = blockIdx.y << 7, bn = blockIdx.x << 7;
    const int mw = (wid & 1) << 6;
    const int nw = (wid >> 1) << 5;

    float acc[4][4][4];
#pragma unroll
    for (int i = 0; i < 4; ++i)
#pragma unroll
        for (int j = 0; j < 4; ++j)
#pragma unroll
            for (int k = 0; k < 4; ++k) acc[i][j][k] = 0.f;

    const int a_r  = (lane & 7) + ((lane & 8) ? 8 : 0);
    const int a_kb = (lane & 16) ? 16 : 0;
    const int b_r  = (lane & 7) + ((lane & 16) ? 8 : 0);
    const int b_kb = (lane & 8) ? 16 : 0;

    uint32_t aoff[4], asw[4];
#pragma unroll
    for (int mi = 0; mi < 4; ++mi) {
        int row = mw + (mi << 4) + a_r;
        aoff[mi] = (uint32_t)(row << 7);
        asw[mi]  = (uint32_t)((row & 7) << 4);
    }
    uint32_t boff[2], bsw[2];
#pragma unroll
    for (int g = 0; g < 2; ++g) {
        int row = nw + (g << 4) + b_r;
        boff[g] = (uint32_t)(row << 7);
        bsw[g]  = (uint32_t)((row & 7) << 4);
    }

    const int KT = K >> 6;
#pragma unroll
    for (int s = 0; s < 2; ++s) {
        load_stage_async(sb + (uint32_t)s * ST_BYTES, A, B, bm, bn, K, s, tid);
        CP_COMMIT();
    }

    int stq = 0;
    for (int kt = 0; kt < KT; ++kt) {
        CP_WAIT1();
        __syncthreads();
        if (kt + 2 < KT) {
            int sn = stq + 2; if (sn >= 3) sn -= 3;
            load_stage_async(sb + (uint32_t)sn * ST_BYTES,
                             A, B, bm, bn, K, kt + 2, tid);
            CP_COMMIT();
        }
        const uint32_t st = sb + (uint32_t)stq * ST_BYTES;
#pragma unroll
        for (int ks = 0; ks < 4; ++ks) {
            uint32_t fbh[2][4];
#pragma unroll
            for (int g = 0; g < 2; ++g)
                ldsm4(fbh[g], st + 16384 + boff[g] +
                      (((uint32_t)(b_kb + ks * 32)) ^ bsw[g]));
#pragma unroll
            for (int mi = 0; mi < 4; ++mi) {
                uint32_t fah[4];
                ldsm4(fah, st + aoff[mi] + (((uint32_t)(a_kb + ks * 32)) ^ asw[mi]));
#pragma unroll
                for (int nj = 0; nj < 4; ++nj)
                    mma_f16(acc[mi][nj], fah, &fbh[nj >> 1][(nj & 1) << 1]);
            }
        }
        if (++stq == 3) stq = 0;
    }

    const int r0 = lane >> 2, c2 = (lane & 3) << 1;
    float2 bb[4];
#pragma unroll
    for (int nj = 0; nj < 4; ++nj)
        bb[nj] = *(const float2*)(bias + bn + nw + (nj << 3) + c2);
#pragma unroll
    for (int mi = 0; mi < 4; ++mi) {
        const int row = bm + mw + (mi << 4) + r0;
#pragma unroll
        for (int nj = 0; nj < 4; ++nj) {
            const int col = bn + nw + (nj << 3) + c2;
            float v0 = acc[mi][nj][0] + bb[nj].x, v1 = acc[mi][nj][1] + bb[nj].y;
            float v2 = acc[mi][nj][2] + bb[nj].x, v3 = acc[mi][nj][3] + bb[nj].y;
            if (RELU) {
                v0 = fmaxf(v0, 0.f); v1 = fmaxf(v1, 0.f);
                v2 = fmaxf(v2, 0.f); v3 = fmaxf(v3, 0.f);
            }
            if (OUT == 0) {
                *(float2*)(Cf + (size_t)row * N + col)       = make_float2(v0, v1);
                *(float2*)(Cf + (size_t)(row + 8) * N + col) = make_float2(v2, v3);
            } else {
                *(uint32_t*)(Ch + (size_t)row * N + col)       = pkh2(v0, v1);
                *(uint32_t*)(Ch + (size_t)(row + 8) * N + col) = pkh2(v2, v3);
            }
        }
    }
}

// --------------------------- flash attention (mma fp16) --------------------
// CTA: 128 threads (4 warps), 64 q-rows (16/warp), 3 CTAs/SM.
// 3 K/V stages + single barrier per ktile (GEMM-style pipeline).
__global__ void __launch_bounds__(128, 3)
flash_mma_kernel(const f16* __restrict__ qkv, const u64* __restrict__ mpack,
                 f16* __restrict__ ctx)
{
    __shared__ f16 sQ[64 * 64];       // 8 KB
    __shared__ f16 sK[3][64 * 64];    // 24 KB
    __shared__ f16 sV[3][64 * 64];    // 24 KB

    const int tid = threadIdx.x, wid = tid >> 5, lane = tid & 31;
    const int q0 = blockIdx.x << 6;
    const int h  = blockIdx.y;
    const int b  = blockIdx.z;

    const uint32_t sqb = s2u(sQ);
    const uint32_t skb[3] = {s2u(sK[0]), s2u(sK[1]), s2u(sK[2])};
    const uint32_t svb[3] = {s2u(sV[0]), s2u(sV[1]), s2u(sV[2])};

    const f16* Qg = qkv + (size_t)(b * 2048) * 3072 + (h << 6);
    const f16* Kg = Qg + 1024;
    const f16* Vg = Qg + 2048;

    // Q tile (group 1)
#pragma unroll
    for (int i = 0; i < 4; ++i) {
        int idx = tid + (i << 7);
        int row = idx >> 3, c = idx & 7;
        cpa16(sqb + SWZ((row << 7) | (c << 4)),
              Qg + (size_t)(q0 + row) * 3072 + (c << 3));
    }
    CP_COMMIT();
    // KV tiles 0,1 (groups 2,3)
#pragma unroll
    for (int s = 0; s < 2; ++s) {
#pragma unroll
        for (int i = 0; i < 4; ++i) {
            int idx = tid + (i << 7);
            int row = idx >> 3, c = idx & 7;
            size_t go = (size_t)(s * 64 + row) * 3072 + (c << 3);
            uint32_t d = SWZ((row << 7) | (c << 4));
            cpa16(skb[s] + d, Kg + go);
            cpa16(svb[s] + d, Vg + go);
        }
        CP_COMMIT();
    }
    CP_WAIT1();      // Q + tile0 complete
    __syncthreads();

    const int a_r  = lane & 15;
    const int a_kb = (lane & 16) ? 16 : 0;
    uint32_t qf[4][4];
    {
        const int row = (wid << 4) + a_r;
        const uint32_t ro = (uint32_t)(row << 7);
        const uint32_t sw = (uint32_t)((row & 7) << 4);
#pragma unroll
        for (int kk = 0; kk < 4; ++kk)
            ldsm4(qf[kk], sqb + ro + (((uint32_t)(a_kb + kk * 32)) ^ sw));
    }

    const int b_r  = (lane & 7) + ((lane & 16) ? 8 : 0);
    const int b_kb = (lane & 8) ? 16 : 0;
    const int v_r  = (lane & 7) + ((lane & 8) ? 8 : 0);
    const int v_kb = (lane & 16) ? 16 : 0;

    const int r0 = lane >> 2, c2 = (lane & 3) << 1;
    const int qrow0 = q0 + (wid << 4) + r0;
    float l0 = 0.f, l1 = 0.f;
    float acc[8][4];
#pragma unroll
    for (int nt = 0; nt < 8; ++nt)
#pragma unroll
        for (int k = 0; k < 4; ++k) acc[nt][k] = 0.f;

    const u64* mp0 = mpack + ((size_t)((b << 4) + h) * 2048 + qrow0) * 32;
    const u64* mp1 = mp0 + 8 * 32;

    int stq = 0;
    for (int kt = 0; kt < 32; ++kt) {
        CP_WAIT1();          // tile kt arrived (only kt+1 may be pending)
        __syncthreads();     // all warps done with stage (kt+2)%3's old tile
        if (kt + 2 < 32) {
            int sn = stq + 2; if (sn >= 3) sn -= 3;
#pragma unroll
            for (int i = 0; i < 4; ++i) {
                int idx = tid + (i << 7);
                int row = idx >> 3, c = idx & 7;
                size_t go = (size_t)((kt + 2) * 64 + row) * 3072 + (c << 3);
                uint32_t d = SWZ((row << 7) | (c << 4));
                cpa16(skb[sn] + d, Kg + go);
                cpa16(svb[sn] + d, Vg + go);
            }
            CP_COMMIT();
        }
        const uint32_t kb = skb[stq], vb = svb[stq];
        const u64 w0 = mp0[kt];
        const u64 w1 = mp1[kt];

        // ---- S = Q K^T ----
        float s[8][4];
#pragma unroll
        for (int nt = 0; nt < 8; ++nt)
#pragma unroll
            for (int k = 0; k < 4; ++k) s[nt][k] = 0.f;
#pragma unroll
        for (int kk = 0; kk < 4; ++kk) {
            uint32_t kf[4][4];
#pragma unroll
            for (int g = 0; g < 4; ++g) {
                int row = (g << 4) + b_r;
                ldsm4(kf[g], kb + (uint32_t)(row << 7) +
                      (((uint32_t)(b_kb + kk * 32)) ^ ((uint32_t)((row & 7) << 4))));
            }
#pragma unroll
            for (int g = 0; g < 4; ++g) {
                mma_f16(s[2 * g],     qf[kk], &kf[g][0]);
                mma_f16(s[2 * g + 1], qf[kk], &kf[g][2]);
            }
        }

        // ---- max-free masked exp ----
#pragma unroll
        for (int nt = 0; nt < 8; ++nt) {
            const int sh = c2 + (nt << 3);
            s[nt][0] = ((w0 >> sh) & 1)       ? __expf(s[nt][0] * 0.125f) : 0.f;
            s[nt][1] = ((w0 >> (sh + 1)) & 1) ? __expf(s[nt][1] * 0.125f) : 0.f;
            s[nt][2] = ((w1 >> sh) & 1)       ? __expf(s[nt][2] * 0.125f) : 0.f;
            s[nt][3] = ((w1 >> (sh + 1)) & 1) ? __expf(s[nt][3] * 0.125f) : 0.f;
            l0 += s[nt][0] + s[nt][1];
            l1 += s[nt][2] + s[nt][3];
        }

        // ---- ctx += P V ----
#pragma unroll
        for (int kk = 0; kk < 4; ++kk) {
            uint32_t ap[4];
            ap[0] = pkh2(s[2 * kk][0],     s[2 * kk][1]);
            ap[1] = pkh2(s[2 * kk][2],     s[2 * kk][3]);
            ap[2] = pkh2(s[2 * kk + 1][0], s[2 * kk + 1][1]);
            ap[3] = pkh2(s[2 * kk + 1][2], s[2 * kk + 1][3]);
            uint32_t vf[4][4];
#pragma unroll
            for (int g = 0; g < 4; ++g) {
                int row = (kk << 4) + v_r;
                ldsm4t(vf[g], vb + (uint32_t)(row << 7) +
                       (((uint32_t)(v_kb + g * 32)) ^ ((uint32_t)((row & 7) << 4))));
            }
#pragma unroll
            for (int g = 0; g < 4; ++g) {
                mma_f16(acc[2 * g],     ap, &vf[g][0]);
                mma_f16(acc[2 * g + 1], ap, &vf[g][2]);
            }
        }

        if (++stq == 3) stq = 0;
    }

    l0 += __shfl_xor_sync(0xffffffffu, l0, 1);
    l0 += __shfl_xor_sync(0xffffffffu, l0, 2);
    l1 += __shfl_xor_sync(0xffffffffu, l1, 1);
    l1 += __shfl_xor_sync(0xffffffffu, l1, 2);

    const float i0 = 1.0f / l0, i1 = 1.0f / l1;
    const size_t row0 = (size_t)(b * 2048 + qrow0) * 1024 + (h << 6) + c2;
    const size_t row1 = row0 + 8 * 1024;
#pragma unroll
    for (int nt = 0; nt < 8; ++nt) {
        *(uint32_t*)(ctx + row0 + (nt << 3)) = pkh2(acc[nt][0] * i0, acc[nt][1] * i0);
        *(uint32_t*)(ctx + row1 + (nt << 3)) = pkh2(acc[nt][2] * i1, acc[nt][3] * i1);
    }
}

// --------------------------- residual + LN --------------------------------
DI float block_sum256(float v, float* red) {
#pragma unroll
    for (int o = 16; o > 0; o >>= 1) v += __shfl_xor_sync(0xffffffffu, v, o);
    const int w = threadIdx.x >> 5;
    if ((threadIdx.x & 31) == 0) red[w] = v;
    __syncthreads();
    if (threadIdx.x < 8) {
        float t = red[threadIdx.x];
#pragma unroll
        for (int o = 4; o > 0; o >>= 1) t += __shfl_xor_sync(0x000000ffu, t, o);
        if (threadIdx.x == 0) red[0] = t;
    }
    __syncthreads();
    float r = red[0];
    __syncthreads();
    return r;
}

template <int SPLIT>
__global__ void __launch_bounds__(256)
add_ln_kernel(const float* __restrict__ X, const float* __restrict__ R,
              const float* __restrict__ g, const float* __restrict__ bt,
              float* __restrict__ out, f16* __restrict__ H)
{
    __shared__ float red[8];
    const int row = blockIdx.x, tid = threadIdx.x;
    const float4 xv = ((const float4*)(X + (size_t)row * 1024))[tid];
    const float4 rv = ((const float4*)(R + (size_t)row * 1024))[tid];
    float v0 = xv.x + rv.x, v1 = xv.y + rv.y, v2 = xv.z + rv.z, v3 = xv.w + rv.w;
    float tot = block_sum256(v0 + v1 + v2 + v3, red);
    const float mu = tot * (1.0f / 1024.0f);
    float d0 = v0 - mu, d1 = v1 - mu, d2 = v2 - mu, d3 = v3 - mu;
    float sq = block_sum256(d0 * d0 + d1 * d1 + d2 * d2 + d3 * d3, red);
    const float rs = rsqrtf(sq * (1.0f / 1024.0f) + 1e-5f);
    const float4 gv = ((const float4*)g)[tid];
    const float4 bv = ((const float4*)bt)[tid];
    float o0 = d0 * rs * gv.x + bv.x, o1 = d1 * rs * gv.y + bv.y;
    float o2 = d2 * rs * gv.z + bv.z, o3 = d3 * rs * gv.w + bv.w;
    ((float4*)(out + (size_t)row * 1024))[tid] = make_float4(o0, o1, o2, o3);
    if (SPLIT) {
        uint2 ph = make_uint2(pkh2(o0, o1), pkh2(o2, o3));
        ((uint2*)(H + (size_t)row * 1024))[tid] = ph;
    }
}

// ------------------------------ launcher -----------------------------------
extern "C" void kernel_launch(void* const* d_in, const int* in_sizes, int n_in,
                              void* d_out, int out_size)
{
    const float* x    = (const float*)d_in[0];
    const void*  mask = d_in[1];
    const float* Wq = (const float*)d_in[2];  const float* bq = (const float*)d_in[3];
    const float* Wk = (const float*)d_in[4];  const float* bk = (const float*)d_in[5];
    const float* Wv = (const float*)d_in[6];  const float* bv = (const float*)d_in[7];
    const float* Wo = (const float*)d_in[8];  const float* bo = (const float*)d_in[9];
    const float* ln1g = (const float*)d_in[10]; const float* ln1b = (const float*)d_in[11];
    const float* ln2g = (const float*)d_in[12]; const float* ln2b = (const float*)d_in[13];
    const float* W1 = (const float*)d_in[14]; const float* b1 = (const float*)d_in[15];
    const float* W2 = (const float*)d_in[16]; const float* b2 = (const float*)d_in[17];
    float* out = (float*)d_out;

    static bool init_done = false;
    static cudaStream_t s1, s2;
    static cudaEvent_t evRoot, evPack, evW;
    if (!init_done) {
        cudaFuncSetAttribute(gemm_mma_kernel<0, 0>, cudaFuncAttributeMaxDynamicSharedMemorySize, GEMM_SMEM);
        cudaFuncSetAttribute(gemm_mma_kernel<0, 1>, cudaFuncAttributeMaxDynamicSharedMemorySize, GEMM_SMEM);
        cudaFuncSetAttribute(gemm_mma_kernel<1, 1>, cudaFuncAttributeMaxDynamicSharedMemorySize, GEMM_SMEM);
        cudaStreamCreateWithFlags(&s1, cudaStreamNonBlocking);
        cudaStreamCreateWithFlags(&s2, cudaStreamNonBlocking);
        cudaEventCreateWithFlags(&evRoot, cudaEventDisableTiming);
        cudaEventCreateWithFlags(&evPack, cudaEventDisableTiming);
        cudaEventCreateWithFlags(&evW,    cudaEventDisableTiming);
        init_done = true;
    }

    float *t0p, *x1p, *bcat;
    u64* mpk;
    f16 *x16, *qkvp, *ctx16, *x116, *h16;
    f16 *wch, *woh, *w1h, *w2h;
    cudaGetSymbolAddress((void**)&t0p, g_t0);
    cudaGetSymbolAddress((void**)&x1p, g_x1);
    cudaGetSymbolAddress((void**)&bcat, g_bcat);
    cudaGetSymbolAddress((void**)&mpk, g_mpack);
    cudaGetSymbolAddress((void**)&x16, g_x16);
    cudaGetSymbolAddress((void**)&qkvp, g_qkv);
    cudaGetSymbolAddress((void**)&ctx16, g_ctx16);
    cudaGetSymbolAddress((void**)&x116, g_x116);
    cudaGetSymbolAddress((void**)&h16, g_h16);
    cudaGetSymbolAddress((void**)&wch, g_wch);
    cudaGetSymbolAddress((void**)&woh, g_woh);
    cudaGetSymbolAddress((void**)&w1h, g_w1h);
    cudaGetSymbolAddress((void**)&w2h, g_w2h);

    // #1 detect
    detect_mask_kernel<<<1, 256>>>((const unsigned int*)mask);
    cudaEventRecord(evRoot, 0);

    // #2 pack (side stream 1)
    cudaStreamWaitEvent(s1, evRoot, 0);
    pack_mask_kernel<<<8192, 256, 0, s1>>>(mask);
    cudaEventRecord(evPack, s1);

    // #3 fused prep
    prep_qkv_kernel<<<3 + 3072 + 4096, 256>>>(x, x16, Wq, Wk, Wv, wch,
                                              bq, bk, bv, bcat);

    // #4 fused QKV GEMM
    gemm_mma_kernel<0, 1><<<dim3(3 * DM / 128, NTOK / 128), 256, GEMM_SMEM>>>(
        x16, wch, bcat, nullptr, qkvp, NTOK, 3 * DM, DM);

    // #5 flash
    cudaStreamWaitEvent(0, evPack, 0);
    flash_mma_kernel<<<dim3(32, 16, 2), 128>>>(qkvp, mpk, ctx16);

    // #6 FFN-weight transposes (side stream 2)
    cudaStreamWaitEvent(s2, evRoot, 0);
    convT_ffn_kernel<<<1024 + 4096 + 4096, 256, 0, s2>>>(Wo, woh, W1, w1h, W2, w2h);
    cudaEventRecord(evW, s2);

    cudaStreamWaitEvent(0, evW, 0);
    gemm_mma_kernel<0, 0><<<dim3(DM / 128, NTOK / 128), 256, GEMM_SMEM>>>(
        ctx16, woh, bo, t0p, nullptr, NTOK, DM, DM);
    add_ln_kernel<1><<<NTOK, 256>>>(x, t0p, ln1g, ln1b, x1p, x116);

    gemm_mma_kernel<1, 1><<<dim3(DFF / 128, NTOK / 128), 256, GEMM_SMEM>>>(
        x116, w1h, b1, nullptr, h16, NTOK, DFF, DM);
    gemm_mma_kernel<0, 0><<<dim3(DM / 128, NTOK / 128), 256, GEMM_SMEM>>>(
        h16, w2h, b2, t0p, nullptr, NTOK, DM, DFF);
    add_ln_kernel<0><<<NTOK, 256>>>(x1p, t0p, ln2g, ln2b, out, nullptr);
}